// round 16
// baseline (speedup 1.0000x reference)
#include <cuda_runtime.h>
#include <cuda_bf16.h>
#include <mma.h>
#include <math.h>

using namespace nvcuda;

#define BATCH 16
#define P1H 97
#define P1W 383
#define C1 32
#define P2H 47
#define P2W 190
#define C2 64
#define FLAT 571520          // 47*190*64
#define KSLICE 640           // 893 * 640 = 571520 exactly
#define NSLICES 893
#define NCHUNK 80            // KSLICE / 8
#define FC_STAGES 4
#define FC_WLD 52                               // 48 cols + 4 pad floats per k-row
#define FC_STAGE_FLOATS (8 * FC_WLD)            // 416 floats per stage
#define FC_WARP_FLOATS (FC_STAGES * FC_STAGE_FLOATS)   // 1664
#define FC_SMEM_BYTES (16 * FC_WARP_FLOATS * 4)        // 106,496 B -> 2 CTAs/SM (213KB)

// conv2 wide-tile geometry: 64 conv cols per CTA
#define CV2_APITCH 2112                          // 66 cols * 32 ch (halfs) per row
#define CV2_BPAD 72
#define CV2_SMEM_BYTES ((6 * CV2_APITCH + 288 * CV2_BPAD) * 2)   // 66,816 B

// ---------------- scratch (device globals; allocations are forbidden) -------
__device__ __align__(128) __nv_bfloat16 g_x1b[(size_t)BATCH * P1H * P1W * C1]; // conv1 out bf16
__device__ __align__(16)  __nv_bfloat16 g_w2b[288 * 64];                       // conv2 weights bf16
__device__ __align__(16)  float g_x2[(size_t)BATCH * FLAT];                    // conv2 out [b][k]
__device__ __align__(128) float g_x2t[(size_t)FLAT * 16];                      // transposed [k][b]
__device__ float g_ypre[512 * 16];   // [n][b]
__device__ float g_zpre[256 * 16];
__device__ float g_y2[256 * 16];
__device__ float g_y3[2925 * 16];
__device__ float g_z4[64 * 16];
__device__ float g_z5[900 * 16];

__device__ __forceinline__ float leaky_f(float x) { return x >= 0.f ? x : 0.01f * x; }

__device__ __forceinline__ unsigned long long pack2(float a, float b) {
    unsigned long long r;
    asm("mov.b64 %0, {%1, %2};" : "=l"(r) : "f"(a), "f"(b));
    return r;
}
__device__ __forceinline__ float2 unpack2(unsigned long long v) {
    float2 r;
    asm("mov.b64 {%0, %1}, %2;" : "=f"(r.x), "=f"(r.y) : "l"(v));
    return r;
}
__device__ __forceinline__ void ffma2(unsigned long long& acc, unsigned long long a, unsigned long long b) {
    asm("fma.rn.f32x2 %0, %1, %2, %0;" : "+l"(acc) : "l"(a), "l"(b));
}

// raw tf32 mma m16n8k8 (documented fragment layout; acc in place)
__device__ __forceinline__ void mma_tf32(float (&d)[4],
                                         unsigned a0, unsigned a1, unsigned a2, unsigned a3,
                                         unsigned b0, unsigned b1) {
    asm volatile(
        "mma.sync.aligned.m16n8k8.row.col.f32.tf32.tf32.f32 "
        "{%0,%1,%2,%3},{%4,%5,%6,%7},{%8,%9},{%0,%1,%2,%3};"
        : "+f"(d[0]), "+f"(d[1]), "+f"(d[2]), "+f"(d[3])
        : "r"(a0), "r"(a1), "r"(a2), "r"(a3), "r"(b0), "r"(b1));
}

// ---------------- prep: conv2 weight -> bf16 ; bias-init split-K accumulators
__global__ void prep_kernel(const float* __restrict__ w2,
                            const float* __restrict__ b512,
                            const float* __restrict__ b256b,
                            const float* __restrict__ bcls,
                            const float* __restrict__ b256a) {
    int i = blockIdx.x * 256 + threadIdx.x;
    if (i < 288 * 64) g_w2b[i] = __float2bfloat16(w2[i]);
    if (i < 512 * 16) g_ypre[i] = b512[i >> 4];
    if (i < 256 * 16) g_zpre[i] = b256b[i >> 4];
    if (i < 256 * 16) g_y2[i] = b256a[i >> 4];
    if (i < 2925 * 16) g_y3[i] = bcls[i >> 4];
}

// ---------------- conv1 (3x3, 1->32) + relu + maxpool2, fused, bf16 output --
__global__ void __launch_bounds__(256) conv1_kernel(const float* __restrict__ hidden,
                                                    const float* __restrict__ w1,
                                                    const float* __restrict__ b1) {
    __shared__ float ins[4 * 768];
    __shared__ float w1s[9 * 32];
    __shared__ float b1s[32];
    int b = blockIdx.y, ph = blockIdx.x;
    int tid = threadIdx.x;

    const float* src = hidden + ((size_t)b * 197 + 2 * ph) * 768;
    for (int i = tid; i < 4 * 768; i += 256) ins[i] = src[i];
    if (tid < 288) w1s[tid] = w1[tid];
    if (tid < 32) b1s[tid] = b1[tid];
    __syncthreads();

    int cg = tid >> 6;
    int pwl = tid & 63;
    int c0 = cg * 8;

    unsigned long long wv2[9][4];
#pragma unroll
    for (int t = 0; t < 9; t++)
#pragma unroll
        for (int p = 0; p < 4; p++)
            wv2[t][p] = pack2(w1s[t * 32 + c0 + 2 * p], w1s[t * 32 + c0 + 2 * p + 1]);

    for (int it = 0; it < 6; it++) {
        int pw = it * 64 + pwl;
        if (pw >= 383) break;
        float in[4][4];
#pragma unroll
        for (int r = 0; r < 4; r++)
#pragma unroll
            for (int c = 0; c < 4; c++) in[r][c] = ins[r * 768 + 2 * pw + c];

        unsigned long long acc2[2][2][4];
#pragma unroll
        for (int i = 0; i < 2; i++)
#pragma unroll
            for (int j = 0; j < 2; j++)
#pragma unroll
                for (int p = 0; p < 4; p++) acc2[i][j][p] = 0ull;

#pragma unroll
        for (int t = 0; t < 9; t++) {
            int kh = t / 3, kw = t % 3;
#pragma unroll
            for (int i = 0; i < 2; i++)
#pragma unroll
                for (int j = 0; j < 2; j++) {
                    float x = in[i + kh][j + kw];
                    unsigned long long xx = pack2(x, x);
#pragma unroll
                    for (int p = 0; p < 4; p++)
                        ffma2(acc2[i][j][p], wv2[t][p], xx);
                }
        }

        size_t o = (((size_t)b * P1H + ph) * P1W + pw) * C1 + c0;
        __nv_bfloat162* dst = reinterpret_cast<__nv_bfloat162*>(g_x1b + o);
#pragma unroll
        for (int p = 0; p < 4; p++) {
            float2 a00 = unpack2(acc2[0][0][p]);
            float2 a01 = unpack2(acc2[0][1][p]);
            float2 a10 = unpack2(acc2[1][0][p]);
            float2 a11 = unpack2(acc2[1][1][p]);
            float m0 = fmaxf(fmaxf(a00.x, a01.x), fmaxf(a10.x, a11.x));
            float m1 = fmaxf(fmaxf(a00.y, a01.y), fmaxf(a10.y, a11.y));
            dst[p] = __floats2bfloat162_rn(fmaxf(m0 + b1s[c0 + 2 * p], 0.f),
                                           fmaxf(m1 + b1s[c0 + 2 * p + 1], 0.f));
        }
    }
}

// ---------------- conv2 (3x3, 32->64) bf16 wmma implicit GEMM + relu + pool --
__global__ void __launch_bounds__(256, 2) conv2_kernel(const float* __restrict__ b2) {
    extern __shared__ __align__(16) __nv_bfloat16 smem_h[];
    __nv_bfloat16* x1s = smem_h;
    __nv_bfloat16* w2s = smem_h + 6 * CV2_APITCH;

    int wt = blockIdx.x;        // 0..5
    int pb = blockIdx.y;        // 0..23
    int b = blockIdx.z;         // 0..15
    int tid = threadIdx.x;
    int h0 = 4 * pb;
    int w0 = wt * 64;

    for (int i = tid; i < 6 * 264; i += 256) {
        int r = i / 264, q = i - r * 264;
        int row = h0 + r; if (row > 96) row = 96;
        int col = w0 + (q >> 2); if (col > 382) col = 382;
        const uint4 v = *(const uint4*)(g_x1b + (((size_t)b * P1H + row) * P1W + col) * C1 + (q & 3) * 8);
        *(uint4*)(x1s + (size_t)r * CV2_APITCH + q * 8) = v;
    }
    for (int i = tid; i < 2304; i += 256) {
        int k = i >> 3, n0 = (i & 7) * 8;
        uint4 v = *(const uint4*)(g_w2b + k * 64 + n0);
        *(uint4*)(w2s + k * CV2_BPAD + n0) = v;
    }
    __syncthreads();

    int wid = tid >> 5;
    int rloc = wid >> 1;
    int hOff = (wid & 1) * 32;

    wmma::fragment<wmma::matrix_a, 16, 16, 16, __nv_bfloat16, wmma::row_major> af[2];
    wmma::fragment<wmma::matrix_b, 16, 16, 16, __nv_bfloat16, wmma::row_major> bf;
    wmma::fragment<wmma::accumulator, 16, 16, 16, float> acc[2][4];
#pragma unroll
    for (int mt = 0; mt < 2; mt++)
#pragma unroll
        for (int nf = 0; nf < 4; nf++) wmma::fill_fragment(acc[mt][nf], 0.f);

#pragma unroll
    for (int kh = 0; kh < 3; kh++) {
        const __nv_bfloat16* base = x1s + (rloc + kh) * CV2_APITCH + hOff * 32;
#pragma unroll
        for (int jc = 0; jc < 6; jc++) {
            wmma::load_matrix_sync(af[0], base + jc * 16, 32);
            wmma::load_matrix_sync(af[1], base + 512 + jc * 16, 32);
            const __nv_bfloat16* bp = w2s + (kh * 96 + jc * 16) * CV2_BPAD;
#pragma unroll
            for (int nf = 0; nf < 4; nf++) {
                wmma::load_matrix_sync(bf, bp + nf * 16, CV2_BPAD);
                wmma::mma_sync(acc[0][nf], af[0], bf, acc[0][nf]);
                wmma::mma_sync(acc[1][nf], af[1], bf, acc[1][nf]);
            }
        }
    }

    __syncthreads();
    float* cs = reinterpret_cast<float*>(smem_h);
#pragma unroll
    for (int mt = 0; mt < 2; mt++)
#pragma unroll
        for (int nf = 0; nf < 4; nf++)
            wmma::store_matrix_sync(cs + (wid * 2 + mt) * 1024 + nf * 16, acc[mt][nf],
                                    64, wmma::mem_row_major);
    __syncthreads();

#pragma unroll
    for (int it = 0; it < 2; it++) {
        int idx = it * 256 + tid;
        int pr = idx >> 8;
        int pj = (idx >> 3) & 31;
        int c0 = (idx & 7) * 8;
        int ph2 = 2 * pb + pr;
        int pwg = wt * 32 + pj;
        if (ph2 < P2H && pwg < P2W) {
            float v[8];
#pragma unroll
            for (int cc = 0; cc < 8; cc++) {
                int c = c0 + cc;
                float m = -1e30f;
#pragma unroll
                for (int i = 0; i < 2; i++)
#pragma unroll
                    for (int j = 0; j < 2; j++) {
                        int rr = 2 * pr + i;
                        int jj = 2 * pj + j;
                        m = fmaxf(m, cs[((rr * 2 + (jj >> 5)) * 2 + ((jj >> 4) & 1)) * 1024
                                        + (jj & 15) * 64 + c]);
                    }
                v[cc] = fmaxf(m + b2[c], 0.f);
            }
            size_t o = (size_t)b * FLAT + ((size_t)ph2 * P2W + pwg) * C2 + c0;
            float4 o0 = {v[0], v[1], v[2], v[3]};
            float4 o1 = {v[4], v[5], v[6], v[7]};
            *reinterpret_cast<float4*>(g_x2 + o) = o0;
            *reinterpret_cast<float4*>(g_x2 + o + 4) = o1;
        }
    }
}

// ---------------- transpose x2[b][k] -> x2t[k][b] ----------------------------
__global__ void __launch_bounds__(256) xpose_kernel() {
    __shared__ float s[640 * 17];
    size_t k0 = (size_t)blockIdx.x * 640;
    int tid = threadIdx.x;
#pragma unroll
    for (int b = 0; b < 16; b++) {
        const float* src = g_x2 + (size_t)b * FLAT + k0;
#pragma unroll
        for (int u = 0; u < 3; u++) {           // 640 = 256*2 + 128
            int kk = tid + u * 256;
            if (kk < 640) s[kk * 17 + b] = __ldcs(src + kk);
        }
    }
    __syncthreads();
    for (int idx = tid; idx < 2560; idx += 256) {
        int k = idx >> 2, q = (idx & 3) * 4;
        const float* sp = s + k * 17 + q;
        float4 v = {sp[0], sp[1], sp[2], sp[3]};
        *reinterpret_cast<float4*>(g_x2t + (k0 + k) * 16 + q) = v;
    }
}

// ---------------- big FC via raw tf32 mma.sync, warp-private cp.async rings --
// 4-stage ring (prefetch depth 3). A loads: contiguous 512B/chunk from x2t,
// L1-shared by all warps (L1 footprint now tiny -> deeper ring is safe).
__global__ void __launch_bounds__(512, 2) fcbig_tf32_kernel(const float* __restrict__ w512,
                                                            const float* __restrict__ w256b) {
    extern __shared__ __align__(16) float ws[];  // [16 warps][4 stages][8][FC_WLD]

    int tid = threadIdx.x;
    int wid = tid >> 5;
    int lane = tid & 31;
    int g = lane >> 2;        // groupID 0..7
    int tig = lane & 3;       // thread-in-group 0..3
    size_t k0 = (size_t)blockIdx.x * KSLICE;

    const float* gsrc[3];
    int gstep[3];
    unsigned soff[3];
#pragma unroll
    for (int i = 0; i < 3; i++) {
        int idx = lane + i * 32;
        int r = idx / 12;
        int c4 = idx - r * 12;
        int gcol = wid * 48 + c4 * 4;
        if (gcol < 512) { gsrc[i] = w512  + (k0 + r) * 512 + gcol;         gstep[i] = 8 * 512; }
        else            { gsrc[i] = w256b + (k0 + r) * 256 + (gcol - 512); gstep[i] = 8 * 256; }
        soff[i] = (unsigned)((r * FC_WLD + c4 * 4) * 4);
    }
    unsigned wbase = (unsigned)__cvta_generic_to_shared(ws) + wid * (FC_WARP_FLOATS * 4);

#define FC_ISSUE(c)                                                               \
    {                                                                             \
        unsigned sb = wbase + ((c) % FC_STAGES) * (FC_STAGE_FLOATS * 4);          \
        _Pragma("unroll")                                                         \
        for (int i = 0; i < 3; i++) {                                             \
            const float* gp = gsrc[i] + (size_t)(c) * gstep[i];                   \
            asm volatile("cp.async.cg.shared.global [%0], [%1], 16;"              \
                         :: "r"(sb + soff[i]), "l"(gp));                          \
        }                                                                         \
        asm volatile("cp.async.commit_group;");                                   \
    }

    FC_ISSUE(0); FC_ISSUE(1); FC_ISSUE(2);

    float acc[6][4];
#pragma unroll
    for (int t = 0; t < 6; t++)
#pragma unroll
        for (int e = 0; e < 4; e++) acc[t][e] = 0.f;

    const unsigned* apl = reinterpret_cast<const unsigned*>(g_x2t + k0 * 16 + tig * 16 + g);
    int lofs0 = tig * FC_WLD + g;
    int lofs1 = (tig + 4) * FC_WLD + g;

    const float* wsw = ws + wid * FC_WARP_FLOATS;
    for (int c = 0; c < NCHUNK; c++) {
        asm volatile("cp.async.wait_group 2;");
        __syncwarp();

        unsigned a0 = __ldg(apl + c * 128);
        unsigned a1 = __ldg(apl + c * 128 + 8);
        unsigned a2 = __ldg(apl + c * 128 + 64);
        unsigned a3 = __ldg(apl + c * 128 + 72);

        const float* buf = wsw + (c % FC_STAGES) * FC_STAGE_FLOATS;
#pragma unroll
        for (int t = 0; t < 6; t++) {
            unsigned b0 = __float_as_uint(buf[lofs0 + t * 8]);
            unsigned b1 = __float_as_uint(buf[lofs1 + t * 8]);
            mma_tf32(acc[t], a0, a1, a2, a3, b0, b1);
        }

        if (c + 3 < NCHUNK) FC_ISSUE(c + 3);
    }
    asm volatile("cp.async.wait_group 0;");
    __syncwarp();

#pragma unroll
    for (int t = 0; t < 6; t++) {
        int col = wid * 48 + t * 8 + tig * 2;
        float* base = (col < 512) ? (g_ypre + col * 16) : (g_zpre + (col - 512) * 16);
        atomicAdd(base + g, acc[t][0]);
        atomicAdd(base + 16 + g, acc[t][1]);
        atomicAdd(base + g + 8, acc[t][2]);
        atomicAdd(base + 16 + g + 8, acc[t][3]);
    }
#undef FC_ISSUE
}

// ---------------- tail1: {split-K y2 (8 CTAs)} || {fused z-chain (1 CTA)} ----
__global__ void __launch_bounds__(128) tail1_kernel(const float* __restrict__ w256a,
                                                    const float* __restrict__ w128a,
                                                    const float* __restrict__ b128a,
                                                    const float* __restrict__ w128b,
                                                    const float* __restrict__ b128b,
                                                    const float* __restrict__ w64,
                                                    const float* __restrict__ b64) {
    __shared__ float xs[384 * 16];
    int tid = threadIdx.x;

    if (blockIdx.x < 8) {
        int nb = blockIdx.x & 1, kh = blockIdx.x >> 1;
        const float* ip = g_ypre + kh * 128 * 16;
        for (int idx = tid; idx < 128 * 16; idx += 128) xs[idx] = leaky_f(ip[idx]);
        __syncthreads();

        int n2 = nb * 128 + tid;
        float acc[16];
#pragma unroll
        for (int b = 0; b < 16; b++) acc[b] = 0.f;
        const float* wp = w256a + (size_t)kh * 128 * 256 + n2;
#pragma unroll 8
        for (int k = 0; k < 128; k++) {
            float wv = __ldg(wp + (size_t)k * 256);
#pragma unroll
            for (int b = 0; b < 16; b++) acc[b] = fmaf(wv, xs[k * 16 + b], acc[b]);
        }
#pragma unroll
        for (int b = 0; b < 16; b++) atomicAdd(g_y2 + n2 * 16 + b, acc[b]);
    } else {
        float* xa = xs;
        float* xb = xs + 256 * 16;
        for (int idx = tid; idx < 256 * 16; idx += 128) xa[idx] = leaky_f(g_zpre[idx]);
        __syncthreads();

        {
            float acc[16];
#pragma unroll
            for (int b = 0; b < 16; b++) acc[b] = 0.f;
#pragma unroll 8
            for (int k = 0; k < 256; k++) {
                float wv = __ldg(w128a + (size_t)k * 128 + tid);
#pragma unroll
                for (int b = 0; b < 16; b++) acc[b] = fmaf(wv, xa[k * 16 + b], acc[b]);
            }
            float bb = b128a[tid];
#pragma unroll
            for (int b = 0; b < 16; b++) xb[tid * 16 + b] = leaky_f(acc[b] + bb);
        }
        __syncthreads();

        {
            float acc[16];
#pragma unroll
            for (int b = 0; b < 16; b++) acc[b] = 0.f;
#pragma unroll 8
            for (int k = 0; k < 128; k++) {
                float wv = __ldg(w128b + (size_t)k * 128 + tid);
#pragma unroll
                for (int b = 0; b < 16; b++) acc[b] = fmaf(wv, xb[k * 16 + b], acc[b]);
            }
            float bb = b128b[tid];
#pragma unroll
            for (int b = 0; b < 16; b++) xa[tid * 16 + b] = leaky_f(acc[b] + bb);
        }
        __syncthreads();

        if (tid < 64) {
            float acc[16];
#pragma unroll
            for (int b = 0; b < 16; b++) acc[b] = 0.f;
#pragma unroll 8
            for (int k = 0; k < 128; k++) {
                float wv = __ldg(w64 + (size_t)k * 64 + tid);
#pragma unroll
                for (int b = 0; b < 16; b++) acc[b] = fmaf(wv, xa[k * 16 + b], acc[b]);
            }
            float bb = b64[tid];
#pragma unroll
            for (int b = 0; b < 16; b++) g_z4[tid * 16 + b] = acc[b] + bb;
        }
    }
}

// ---------------- tail2: {split-K y3 (46 CTAs)} || {z5 FC (8 CTAs)} ---------
__global__ void __launch_bounds__(128) tail2_kernel(const float* __restrict__ wcls,
                                                    const float* __restrict__ wreg,
                                                    const float* __restrict__ breg) {
    __shared__ float xs[128 * 16];
    int tid = threadIdx.x;

    if (blockIdx.x < 46) {
        int nb = blockIdx.x % 23, kh = blockIdx.x / 23;
        const float* ip = g_y2 + kh * 128 * 16;
        for (int idx = tid; idx < 128 * 16; idx += 128) xs[idx] = leaky_f(ip[idx]);
        __syncthreads();

        int n2 = nb * 128 + tid;
        if (n2 < 2925) {
            float acc[16];
#pragma unroll
            for (int b = 0; b < 16; b++) acc[b] = 0.f;
            const float* wp = wcls + (size_t)kh * 128 * 2925 + n2;
#pragma unroll 8
            for (int k = 0; k < 128; k++) {
                float wv = __ldg(wp + (size_t)k * 2925);
#pragma unroll
                for (int b = 0; b < 16; b++) acc[b] = fmaf(wv, xs[k * 16 + b], acc[b]);
            }
#pragma unroll
            for (int b = 0; b < 16; b++) atomicAdd(g_y3 + n2 * 16 + b, acc[b]);
        }
    } else {
        int bx = blockIdx.x - 46;
        for (int idx = tid; idx < 64 * 16; idx += 128) xs[idx] = leaky_f(g_z4[idx]);
        __syncthreads();

        int n2 = bx * 128 + tid;
        if (n2 < 900) {
            float acc[16];
#pragma unroll
            for (int b = 0; b < 16; b++) acc[b] = 0.f;
#pragma unroll 8
            for (int k = 0; k < 64; k++) {
                float wv = __ldg(wreg + (size_t)k * 900 + n2);
#pragma unroll
                for (int b = 0; b < 16; b++) acc[b] = fmaf(wv, xs[k * 16 + b], acc[b]);
            }
            float bb = breg[n2];
#pragma unroll
            for (int b = 0; b < 16; b++) g_z5[n2 * 16 + b] = acc[b] + bb;
        }
    }
}

// ---------------- heads: softmax(leaky(y3)@wsm+bsm), sigmoid(leaky(z5)@wsig+bsig)
__global__ void heads_kernel(const float* __restrict__ wsm, const float* __restrict__ bsm,
                             const float* __restrict__ wsig, const float* __restrict__ bsig,
                             float* __restrict__ out) {
    int idx = blockIdx.x * 256 + threadIdx.x;
    if (idx < 3600) {
        int b = idx / 225, p = idx % 225;
        float yv[13];
#pragma unroll
        for (int i = 0; i < 13; i++) yv[i] = leaky_f(g_y3[(p * 13 + i) * 16 + b]);
        float l[13];
        float m = -1e30f;
#pragma unroll
        for (int o = 0; o < 13; o++) {
            float s = bsm[o];
#pragma unroll
            for (int i = 0; i < 13; i++) s = fmaf(yv[i], wsm[i * 13 + o], s);
            l[o] = s;
            m = fmaxf(m, s);
        }
        float sum = 0.f;
#pragma unroll
        for (int o = 0; o < 13; o++) { l[o] = expf(l[o] - m); sum += l[o]; }
        float inv = 1.f / sum;
        float* dst = out + (size_t)(b * 225 + p) * 13;
#pragma unroll
        for (int o = 0; o < 13; o++) dst[o] = l[o] * inv;
    } else if (idx < 7200) {
        int j = idx - 3600;
        int b = j / 225, p = j % 225;
        float zv[4];
#pragma unroll
        for (int i = 0; i < 4; i++) zv[i] = leaky_f(g_z5[(p * 4 + i) * 16 + b]);
        float* dst = out + 46800 + (size_t)(b * 225 + p) * 4;
#pragma unroll
        for (int o = 0; o < 4; o++) {
            float s = bsig[o];
#pragma unroll
            for (int i = 0; i < 4; i++) s = fmaf(zv[i], wsig[i * 4 + o], s);
            dst[o] = 1.f / (1.f + expf(-s));
        }
    }
}

// ---------------- launch ----------------------------------------------------
extern "C" void kernel_launch(void* const* d_in, const int* in_sizes, int n_in,
                              void* d_out, int out_size) {
    const float* hidden  = (const float*)d_in[0];
    const float* conv1_w = (const float*)d_in[1];
    const float* conv1_b = (const float*)d_in[2];
    const float* conv2_w = (const float*)d_in[3];
    const float* conv2_b = (const float*)d_in[4];
    const float* w512    = (const float*)d_in[5];
    const float* b512    = (const float*)d_in[6];
    const float* w256a   = (const float*)d_in[7];
    const float* b256a   = (const float*)d_in[8];
    const float* wcls    = (const float*)d_in[9];
    const float* bcls    = (const float*)d_in[10];
    const float* wsm     = (const float*)d_in[11];
    const float* bsm     = (const float*)d_in[12];
    const float* w256b   = (const float*)d_in[13];
    const float* b256b   = (const float*)d_in[14];
    const float* w128a   = (const float*)d_in[15];
    const float* b128a   = (const float*)d_in[16];
    const float* w128b   = (const float*)d_in[17];
    const float* b128b   = (const float*)d_in[18];
    const float* w64     = (const float*)d_in[19];
    const float* b64     = (const float*)d_in[20];
    const float* wreg    = (const float*)d_in[21];
    const float* breg    = (const float*)d_in[22];
    const float* wsig    = (const float*)d_in[23];
    const float* bsig    = (const float*)d_in[24];
    float* out = (float*)d_out;

    static bool attr_set = false;
    if (!attr_set) {
        cudaFuncSetAttribute(conv2_kernel, cudaFuncAttributeMaxDynamicSharedMemorySize, CV2_SMEM_BYTES);
        cudaFuncSetAttribute(fcbig_tf32_kernel, cudaFuncAttributeMaxDynamicSharedMemorySize, FC_SMEM_BYTES);
        attr_set = true;
    }

    prep_kernel<<<183, 256>>>(conv2_w, b512, b256b, bcls, b256a);
    conv1_kernel<<<dim3(P1H, BATCH), 256>>>(hidden, conv1_w, conv1_b);
    conv2_kernel<<<dim3(6, 24, BATCH), 256, CV2_SMEM_BYTES>>>(conv2_b);
    xpose_kernel<<<NSLICES, 256>>>();
    fcbig_tf32_kernel<<<NSLICES, 512, FC_SMEM_BYTES>>>(w512, w256b);

    tail1_kernel<<<9, 128>>>(w256a, w128a, b128a, w128b, b128b, w64, b64);
    tail2_kernel<<<54, 128>>>(wcls, wreg, breg);

    heads_kernel<<<29, 256>>>(wsm, bsm, wsig, bsig, out);
}